// round 12
// baseline (speedup 1.0000x reference)
#include <cuda_runtime.h>
#include <cuda_fp16.h>
#include <cstdint>

#define NN 100000
#define NE 1600000
#define H  128
#define SCAN_NB 98           // ceil(NN/1024)
#define GEMM_GRID 782        // ceil(NN/128)
#define FILL_GRID 6250       // NE/256
#define AGG_GRID 3125        // NN/32, 128-thr blocks
#define PREPW_BLOCKS 192     // 3 layers x 64 blocks

// ---------------- scratch (zero at load; every call restores zeros after use) ----------
__device__ unsigned long long g_pack[NN];   // cnt<<40 | fixed-point weighted degree
__device__ float  g_dis[NN];
__device__ int    g_rowptr[NN + 1];
__device__ int    g_cursor[NN];
__device__ int    g_bsum[SCAN_NB];
__device__ int    g_flag[SCAN_NB];
__device__ __align__(16) int2 g_srcw[NE + 2];
__device__ __align__(16) __half g_hh[(size_t)NN * H];      // GEMM out (gather source)
__device__ __align__(16) __half g_oh[3][(size_t)NN * H];   // layer outputs, fp16
__device__ __align__(16) __half g_whalf[3][H * H];         // fp16 W, row-major [k][n]
__device__ double g_sums[6 * H];                           // zeroed by prepw each call

__device__ __forceinline__ uint32_t smem_u32(const void* p) {
    uint32_t a;
    asm("{ .reg .u64 t; cvta.to.shared.u64 t, %1; cvt.u32.u64 %0, t; }" : "=r"(a) : "l"(p));
    return a;
}

// BN scale/shift from accumulated sums (computed inline by consumers)
__device__ __forceinline__ void bn_from_sums(int layer, int c,
                                             const float* __restrict__ g,
                                             const float* __restrict__ be,
                                             float& sc, float& sh) {
    double s  = g_sums[layer * 256 + c];
    double ss = g_sums[layer * 256 + 128 + c];
    double mean = s * (1.0 / NN);
    double var  = ss * (1.0 / NN) - mean * mean;
    float inv = (float)(1.0 / sqrt(var + 1e-5));
    sc = g[c] * inv;
    sh = be[c] - (float)mean * sc;
}

// ---------------- launch 1: W fp16 prep + zero g_sums + reset scan flags ----------------
__global__ void prepw_kernel(const float* __restrict__ W1, const float* __restrict__ W2,
                             const float* __restrict__ W3) {
    int b = blockIdx.x;
    if (b < PREPW_BLOCKS) {
        int l = b >> 6;
        const float* W = (l == 0) ? W1 : (l == 1) ? W2 : W3;
        int idx = (b & 63) * 256 + threadIdx.x;
        g_whalf[l][idx] = __float2half_rn(W[idx]);
        return;
    }
    int zb = b - PREPW_BLOCKS;
    int i = zb * 256 + threadIdx.x;
    if (i < 6 * H) g_sums[i] = 0.0;
    if (zb == 0 && threadIdx.x < SCAN_NB) g_flag[threadIdx.x] = 0;
}

// ---------------- launch 2: packed degree+count accumulation ----------------
__global__ void degcnt_kernel(const int* __restrict__ ei,
                              const float* __restrict__ ew) {
    int e = blockIdx.x * blockDim.x + threadIdx.x;
    if (e >= NE) return;
    int c = __ldcs(&ei[NE + e]);
    if ((unsigned)c >= NN) return;
    float w = __ldcs(&ew[e]);
    unsigned long long val =
        (1ULL << 40) | (unsigned long long)__float2uint_rn(w * 16777216.0f);
    atomicAdd(&g_pack[c], val);
}

// ---------------- launch 3: dis + single-kernel scan; restores g_pack=0 ----------------
__global__ void __launch_bounds__(1024) scandis_kernel() {
    __shared__ int wsum[32];
    __shared__ int s_pred[128];
    __shared__ int s_off;
    int tid = threadIdx.x, lane = tid & 31, wd = tid >> 5;
    int b = blockIdx.x;
    int i = b * 1024 + tid;

    int v = 0;
    if (i < NN) {
        unsigned long long p = g_pack[i];
        g_pack[i] = 0ULL;
        v = (int)(p >> 40);
        float deg = (float)((double)(p & 0xFFFFFFFFFFULL) * (1.0 / 16777216.0));
        g_dis[i] = rsqrtf(deg + 1.0f);   // +1 = self-loop weight
    }

    int x = v;
    #pragma unroll
    for (int off = 1; off < 32; off <<= 1) {
        int y = __shfl_up_sync(0xffffffffu, x, off);
        if (lane >= off) x += y;
    }
    if (lane == 31) wsum[wd] = x;
    __syncthreads();
    if (wd == 0) {
        int s = wsum[lane];
        #pragma unroll
        for (int off = 1; off < 32; off <<= 1) {
            int y = __shfl_up_sync(0xffffffffu, s, off);
            if (lane >= off) s += y;
        }
        wsum[lane] = s;
    }
    __syncthreads();
    int woff = wd ? wsum[wd - 1] : 0;
    int incl = x + woff;

    if (tid == 1023) {
        g_bsum[b] = incl;
        __threadfence();
        atomicExch(&g_flag[b], 1);
    }
    if (tid < b) {
        while (atomicAdd(&g_flag[tid], 0) == 0) {}
        __threadfence();
        s_pred[tid] = __ldcg(&g_bsum[tid]);
    }
    __syncthreads();
    int val = (tid < b) ? s_pred[tid] : 0;
    #pragma unroll
    for (int off = 16; off > 0; off >>= 1)
        val += __shfl_down_sync(0xffffffffu, val, off);
    __syncthreads();
    if (lane == 0) wsum[wd] = val;
    __syncthreads();
    if (tid == 0) {
        int s = 0;
        #pragma unroll
        for (int k = 0; k < 4; k++) s += wsum[k];
        s_off = s;
    }
    __syncthreads();
    int off2 = s_off;
    if (i < NN) {
        int rp = incl - v + off2;
        g_rowptr[i] = rp;
        g_cursor[i] = rp;
    }
    if (b == SCAN_NB - 1 && tid == 1023) g_rowptr[NN] = off2 + incl;
}

// ---------------- HMMA GEMM body ----------------
#define APAD 72
#define BPAD 136
__device__ __forceinline__ void gemm_body(
    const float* __restrict__ Aext, int osel, int bnlayer,
    const float* __restrict__ bng, const float* __restrict__ bnbe, int wsel, int bid,
    __half (*s_a)[APAD], __half (*s_b)[BPAD], float* s_sc, float* s_sh) {
    int tid = threadIdx.x, wid = tid >> 5, lane = tid & 31;
    int warp_m = wid & 3;
    int warp_n = wid >> 2;
    int m0 = bid * 128;
    bool dobn = (bnlayer >= 0);

    if (dobn && tid < H) {
        float sc, sh;
        bn_from_sums(bnlayer, tid, bng, bnbe, sc, sh);
        s_sc[tid] = sc;
        s_sh[tid] = sh;
    }
    __syncthreads();

    float d[2][8][4];
    #pragma unroll
    for (int mt = 0; mt < 2; mt++)
        #pragma unroll
        for (int nt = 0; nt < 8; nt++)
            #pragma unroll
            for (int r = 0; r < 4; r++) d[mt][nt][r] = 0.f;

    for (int kc = 0; kc < 2; kc++) {
        int kbase = kc * 64;
        #pragma unroll
        for (int i = 0; i < 8; i++) {
            int idx = i * 256 + tid;
            int m = idx >> 4, q = idx & 15;
            int gm = m0 + m;
            float4 v = make_float4(0.f, 0.f, 0.f, 0.f);
            if (gm < NN) {
                if (osel < 0) {
                    v = ((const float4*)Aext)[(size_t)gm * 32 + (kbase >> 2) + q];
                } else {
                    uint2 hv = *(const uint2*)&g_oh[osel][(size_t)gm * 128 + kbase + q * 4];
                    float2 f0 = __half22float2(*(__half2*)&hv.x);
                    float2 f1 = __half22float2(*(__half2*)&hv.y);
                    v = make_float4(f0.x, f0.y, f1.x, f1.y);
                }
                if (dobn) {
                    int k = kbase + q * 4;
                    v.x = fmaxf(fmaf(v.x, s_sc[k + 0], s_sh[k + 0]), 0.f);
                    v.y = fmaxf(fmaf(v.y, s_sc[k + 1], s_sh[k + 1]), 0.f);
                    v.z = fmaxf(fmaf(v.z, s_sc[k + 2], s_sh[k + 2]), 0.f);
                    v.w = fmaxf(fmaf(v.w, s_sc[k + 3], s_sh[k + 3]), 0.f);
                }
            }
            __half2 h0 = __floats2half2_rn(v.x, v.y);
            __half2 h1 = __floats2half2_rn(v.z, v.w);
            *(uint2*)&s_a[m][q * 4] = make_uint2(*(unsigned*)&h0, *(unsigned*)&h1);
        }
        #pragma unroll
        for (int i = 0; i < 4; i++) {
            int idx = i * 256 + tid;
            int k = idx >> 4, n16 = idx & 15;
            *(uint4*)&s_b[k][n16 * 8] =
                *(const uint4*)&g_whalf[wsel][(size_t)(kbase + k) * 128 + n16 * 8];
        }
        __syncthreads();

        #pragma unroll
        for (int kt = 0; kt < 4; kt++) {
            uint32_t a[2][4];
            #pragma unroll
            for (int mt = 0; mt < 2; mt++) {
                uint32_t addr = smem_u32(
                    &s_a[warp_m * 32 + mt * 16 + (lane & 15)][kt * 16 + (lane >> 4) * 8]);
                asm volatile("ldmatrix.sync.aligned.m8n8.x4.shared.b16 {%0,%1,%2,%3}, [%4];"
                             : "=r"(a[mt][0]), "=r"(a[mt][1]), "=r"(a[mt][2]), "=r"(a[mt][3])
                             : "r"(addr));
            }
            #pragma unroll
            for (int ng = 0; ng < 4; ng++) {
                uint32_t b0, b1, b2, b3;
                uint32_t addr = smem_u32(
                    &s_b[kt * 16 + (lane & 15)][warp_n * 64 + ng * 16 + (lane >> 4) * 8]);
                asm volatile("ldmatrix.sync.aligned.m8n8.x4.trans.shared.b16 {%0,%1,%2,%3}, [%4];"
                             : "=r"(b0), "=r"(b1), "=r"(b2), "=r"(b3) : "r"(addr));
                #pragma unroll
                for (int mt = 0; mt < 2; mt++) {
                    asm volatile(
                        "mma.sync.aligned.m16n8k16.row.col.f32.f16.f16.f32 "
                        "{%0,%1,%2,%3}, {%4,%5,%6,%7}, {%8,%9}, {%0,%1,%2,%3};"
                        : "+f"(d[mt][ng*2][0]), "+f"(d[mt][ng*2][1]),
                          "+f"(d[mt][ng*2][2]), "+f"(d[mt][ng*2][3])
                        : "r"(a[mt][0]), "r"(a[mt][1]), "r"(a[mt][2]), "r"(a[mt][3]),
                          "r"(b0), "r"(b1));
                    asm volatile(
                        "mma.sync.aligned.m16n8k16.row.col.f32.f16.f16.f32 "
                        "{%0,%1,%2,%3}, {%4,%5,%6,%7}, {%8,%9}, {%0,%1,%2,%3};"
                        : "+f"(d[mt][ng*2+1][0]), "+f"(d[mt][ng*2+1][1]),
                          "+f"(d[mt][ng*2+1][2]), "+f"(d[mt][ng*2+1][3])
                        : "r"(a[mt][0]), "r"(a[mt][1]), "r"(a[mt][2]), "r"(a[mt][3]),
                          "r"(b2), "r"(b3));
                }
            }
        }
        __syncthreads();
    }

    int mrow = m0 + warp_m * 32 + (lane >> 2);
    int ncol = warp_n * 64 + (lane & 3) * 2;
    #pragma unroll
    for (int mt = 0; mt < 2; mt++) {
        int r0 = mrow + mt * 16;
        int r1 = r0 + 8;
        #pragma unroll
        for (int nt = 0; nt < 8; nt++) {
            int c = ncol + nt * 8;
            if (r0 < NN) {
                __half2 h = __floats2half2_rn(d[mt][nt][0], d[mt][nt][1]);
                *(__half2*)&g_hh[(size_t)r0 * 128 + c] = h;
            }
            if (r1 < NN) {
                __half2 h = __floats2half2_rn(d[mt][nt][2], d[mt][nt][3]);
                *(__half2*)&g_hh[(size_t)r1 * 128 + c] = h;
            }
        }
    }
}

// ---------------- launch 4 (captured): fused fill (CSR) + gemm layer1 ----------------
__global__ void __launch_bounds__(256)
fillgemm_kernel(const float* __restrict__ x, const int* __restrict__ ei,
                const float* __restrict__ ew) {
    __shared__ __align__(16) __half s_a[128][APAD];
    __shared__ __align__(16) __half s_b[64][BPAD];
    __shared__ float s_sc[H], s_sh[H];
    if (blockIdx.x < GEMM_GRID) {
        gemm_body(x, -1, -1, nullptr, nullptr, 0, blockIdx.x, s_a, s_b, s_sc, s_sh);
        return;
    }
    int e = (blockIdx.x - GEMM_GRID) * 256 + threadIdx.x;
    if (e >= NE) return;
    int r = __ldcs(&ei[e]);
    int c = __ldcs(&ei[NE + e]);
    if ((unsigned)r >= NN || (unsigned)c >= NN) return;
    int pos = atomicAdd(&g_cursor[c], 1);
    float w = g_dis[r] * __ldcs(&ew[e]) * g_dis[c];
    g_srcw[pos] = make_int2(r, __float_as_int(w));
}

// gemm for layers 2/3 (fp16 A, BN computed inline from g_sums)
__global__ void __launch_bounds__(256)
gemm_kernel(int osel, int bnlayer, const float* __restrict__ bng,
            const float* __restrict__ bnbe, int wsel) {
    __shared__ __align__(16) __half s_a[128][APAD];
    __shared__ __align__(16) __half s_b[64][BPAD];
    __shared__ float s_sc[H], s_sh[H];
    gemm_body(nullptr, osel, bnlayer, bng, bnbe, wsel, blockIdx.x, s_a, s_b, s_sc, s_sh);
}

// ---------------- agg: 128 threads, 12 blocks/SM, fp16 out, reg-level BN stats --------
__device__ __forceinline__ void fma_half4(float4& acc, float w, unsigned lo, unsigned hi) {
    __half2 p0 = *(__half2*)&lo, p1 = *(__half2*)&hi;
    float2 f0 = __half22float2(p0), f1 = __half22float2(p1);
    acc.x = fmaf(w, f0.x, acc.x); acc.y = fmaf(w, f0.y, acc.y);
    acc.z = fmaf(w, f1.x, acc.z); acc.w = fmaf(w, f1.y, acc.w);
}

__global__ void __launch_bounds__(128, 12)
agg_kernel(const float* __restrict__ bias, int osel, int layer) {
    __shared__ float s_v[4][132];
    __half* outb = g_oh[osel];
    int wid  = threadIdx.x >> 5;
    int lane = threadIdx.x & 31;
    float4 b4 = ((const float4*)bias)[lane];
    float4 s4 = make_float4(0.f, 0.f, 0.f, 0.f);
    float4 q4 = make_float4(0.f, 0.f, 0.f, 0.f);
    int base = blockIdx.x * 32 + wid * 8;

    for (int n = 0; n < 8; n++) {
        int gw = base + n;
        if (gw < NN) {
            float dii = g_dis[gw];
            float swt = dii * dii;
            uint2 sv = __ldg((const uint2*)&g_hh[(size_t)gw * 128 + lane * 4]);
            float4 acc = make_float4(0.f, 0.f, 0.f, 0.f);
            fma_half4(acc, swt, sv.x, sv.y);
            int p  = __ldg(&g_rowptr[gw]);
            int pe = __ldg(&g_rowptr[gw + 1]);
            if ((p & 1) && p < pe) {
                int2  sw = __ldcs(&g_srcw[p]);
                uint2 v  = __ldg((const uint2*)&g_hh[(size_t)sw.x * 128 + lane * 4]);
                fma_half4(acc, __int_as_float(sw.y), v.x, v.y);
                ++p;
            }
            if (p + 3 < pe) {
                int4 c0 = __ldcs((const int4*)&g_srcw[p]);
                int4 c1 = __ldcs((const int4*)&g_srcw[p + 2]);
                for (; p + 7 < pe; p += 4) {
                    int4 n0 = __ldcs((const int4*)&g_srcw[p + 4]);
                    int4 n1 = __ldcs((const int4*)&g_srcw[p + 6]);
                    uint2 v0 = __ldg((const uint2*)&g_hh[(size_t)c0.x * 128 + lane * 4]);
                    uint2 v1 = __ldg((const uint2*)&g_hh[(size_t)c0.z * 128 + lane * 4]);
                    uint2 v2 = __ldg((const uint2*)&g_hh[(size_t)c1.x * 128 + lane * 4]);
                    uint2 v3 = __ldg((const uint2*)&g_hh[(size_t)c1.z * 128 + lane * 4]);
                    fma_half4(acc, __int_as_float(c0.y), v0.x, v0.y);
                    fma_half4(acc, __int_as_float(c0.w), v1.x, v1.y);
                    fma_half4(acc, __int_as_float(c1.y), v2.x, v2.y);
                    fma_half4(acc, __int_as_float(c1.w), v3.x, v3.y);
                    c0 = n0; c1 = n1;
                }
                uint2 v0 = __ldg((const uint2*)&g_hh[(size_t)c0.x * 128 + lane * 4]);
                uint2 v1 = __ldg((const uint2*)&g_hh[(size_t)c0.z * 128 + lane * 4]);
                uint2 v2 = __ldg((const uint2*)&g_hh[(size_t)c1.x * 128 + lane * 4]);
                uint2 v3 = __ldg((const uint2*)&g_hh[(size_t)c1.z * 128 + lane * 4]);
                fma_half4(acc, __int_as_float(c0.y), v0.x, v0.y);
                fma_half4(acc, __int_as_float(c0.w), v1.x, v1.y);
                fma_half4(acc, __int_as_float(c1.y), v2.x, v2.y);
                fma_half4(acc, __int_as_float(c1.w), v3.x, v3.y);
                p += 4;
            }
            for (; p < pe; ++p) {
                int2  sw = __ldcs(&g_srcw[p]);
                uint2 v  = __ldg((const uint2*)&g_hh[(size_t)sw.x * 128 + lane * 4]);
                fma_half4(acc, __int_as_float(sw.y), v.x, v.y);
            }
            acc.x += b4.x; acc.y += b4.y; acc.z += b4.z; acc.w += b4.w;
            __half2 h0 = __floats2half2_rn(acc.x, acc.y);
            __half2 h1 = __floats2half2_rn(acc.z, acc.w);
            *(uint2*)&outb[(size_t)gw * 128 + lane * 4] =
                make_uint2(*(unsigned*)&h0, *(unsigned*)&h1);
            s4.x += acc.x; s4.y += acc.y; s4.z += acc.z; s4.w += acc.w;
            q4.x = fmaf(acc.x, acc.x, q4.x); q4.y = fmaf(acc.y, acc.y, q4.y);
            q4.z = fmaf(acc.z, acc.z, q4.z); q4.w = fmaf(acc.w, acc.w, q4.w);
        }
    }

    *((float4*)&s_v[wid][lane * 4]) = s4;
    __syncthreads();
    int c = threadIdx.x;
    {
        float s = 0.f;
        #pragma unroll
        for (int w4 = 0; w4 < 4; w4++) s += s_v[w4][c];
        atomicAdd(&g_sums[layer * 256 + c], (double)s);
    }
    __syncthreads();
    *((float4*)&s_v[wid][lane * 4]) = q4;
    __syncthreads();
    {
        float q = 0.f;
        #pragma unroll
        for (int w4 = 0; w4 < 4; w4++) q += s_v[w4][c];
        atomicAdd(&g_sums[layer * 256 + 128 + c], (double)q);
    }
}

// ---------------- readout (BN computed inline for all 3 layers) ----------------
__global__ void __launch_bounds__(320)
linear_kernel(const float* __restrict__ Wlin, const float* __restrict__ blin,
              const float* __restrict__ g1, const float* __restrict__ be1,
              const float* __restrict__ g2, const float* __restrict__ be2,
              const float* __restrict__ g3, const float* __restrict__ be3,
              float* __restrict__ out) {
    __shared__ float s_wt[10][388];
    __shared__ float s_emb[32][388];
    __shared__ float s_b[10];
    __shared__ float s_sc[384], s_sh[384];
    int tid = threadIdx.x;
    for (int i = tid; i < 3840; i += 320) s_wt[i % 10][i / 10] = Wlin[i];
    for (int i = tid; i < 384; i += 320) {
        int l = i >> 7, c = i & 127;
        const float* g  = (l == 0) ? g1  : (l == 1) ? g2  : g3;
        const float* be = (l == 0) ? be1 : (l == 1) ? be2 : be3;
        float sc, sh;
        bn_from_sums(l, c, g, be, sc, sh);
        s_sc[i] = sc;
        s_sh[i] = sh;
    }
    if (tid < 10) s_b[tid] = blin[tid];
    int nb = blockIdx.x * 32;
    __syncthreads();

    for (int i = tid; i < 3072; i += 320) {
        int node = i / 96, q = i % 96;
        int gn = nb + node;
        float4 v = make_float4(0.f, 0.f, 0.f, 0.f);
        if (gn < NN) {
            int l = q >> 5, qq = q & 31;
            uint2 hv = *(const uint2*)&g_oh[l][(size_t)gn * 128 + qq * 4];
            float2 f0 = __half22float2(*(__half2*)&hv.x);
            float2 f1 = __half22float2(*(__half2*)&hv.y);
            v = make_float4(f0.x, f0.y, f1.x, f1.y);
        }
        int f = q * 4;
        v.x = fmaxf(fmaf(v.x, s_sc[f + 0], s_sh[f + 0]), 0.f);
        v.y = fmaxf(fmaf(v.y, s_sc[f + 1], s_sh[f + 1]), 0.f);
        v.z = fmaxf(fmaf(v.z, s_sc[f + 2], s_sh[f + 2]), 0.f);
        v.w = fmaxf(fmaf(v.w, s_sc[f + 3], s_sh[f + 3]), 0.f);
        *((float4*)&s_emb[node][f]) = v;
    }
    __syncthreads();

    int node = tid / 10, c = tid % 10;
    int gn = nb + node;
    if (gn < NN) {
        const float4* e = (const float4*)&s_emb[node][0];
        const float4* w = (const float4*)&s_wt[c][0];
        float acc = 0.f;
        #pragma unroll
        for (int j = 0; j < 96; j++) {
            float4 v = e[j], ww = w[j];
            acc += v.x * ww.x + v.y * ww.y + v.z * ww.z + v.w * ww.w;
        }
        out[(size_t)gn * 10 + c] = acc + s_b[c];
    }
}

// ---------------- host launcher ----------------
extern "C" void kernel_launch(void* const* d_in, const int* in_sizes, int n_in,
                              void* d_out, int out_size) {
    const float* x    = (const float*)d_in[0];
    const int*   ei   = (const int*)d_in[1];
    const float* ew   = (const float*)d_in[2];
    const float* W1  = (const float*)d_in[3];
    const float* b1  = (const float*)d_in[4];
    const float* g1  = (const float*)d_in[5];
    const float* be1 = (const float*)d_in[6];
    const float* W2  = (const float*)d_in[7];
    const float* b2  = (const float*)d_in[8];
    const float* g2  = (const float*)d_in[9];
    const float* be2 = (const float*)d_in[10];
    const float* W3  = (const float*)d_in[11];
    const float* b3  = (const float*)d_in[12];
    const float* g3  = (const float*)d_in[13];
    const float* be3 = (const float*)d_in[14];
    const float* Wlin = (const float*)d_in[15];
    const float* blin = (const float*)d_in[16];
    float* out = (float*)d_out;

    prepw_kernel<<<PREPW_BLOCKS + 3, 256>>>(W1, W2, W3);          // 1
    degcnt_kernel<<<FILL_GRID, 256>>>(ei, ew);                    // 2
    scandis_kernel<<<SCAN_NB, 1024>>>();                          // 3
    fillgemm_kernel<<<GEMM_GRID + FILL_GRID, 256>>>(x, ei, ew);   // 4 <- ncu slot

    agg_kernel<<<AGG_GRID, 128>>>(b1, 0, 0);                      // 5
    gemm_kernel<<<GEMM_GRID, 256>>>(0, 0, g1, be1, 1);            // 6
    agg_kernel<<<AGG_GRID, 128>>>(b2, 1, 1);                      // 7
    gemm_kernel<<<GEMM_GRID, 256>>>(1, 1, g2, be2, 2);            // 8
    agg_kernel<<<AGG_GRID, 128>>>(b3, 2, 2);                      // 9
    linear_kernel<<<(NN + 31) / 32, 320>>>(Wlin, blin, g1, be1, g2, be2, g3, be3, out); // 10
    (void)in_sizes; (void)n_in; (void)out_size;
}

// round 13
// speedup vs baseline: 1.1599x; 1.1599x over previous
#include <cuda_runtime.h>
#include <cuda_fp16.h>
#include <cstdint>

#define NN 100000
#define NE 1600000
#define H  128
#define SCAN_NB 98           // ceil(NN/1024)
#define GEMM_GRID 782        // ceil(NN/128)
#define FILL_GRID 6250       // NE/256
#define AGG_GRID 1563        // ceil(NN/64), 256-thr blocks
#define PREPW_BLOCKS 192     // 3 layers x 64 blocks
#define DEG_BASE 193         // degcnt blocks start here in prep_kernel

// ---------------- scratch (zero at load; every call restores zeros after use) ----------
__device__ unsigned long long g_pack[NN];   // cnt<<40 | fixed-point weighted degree
__device__ float  g_dis[NN];
__device__ int    g_rowptr[NN + 1];
__device__ int    g_cursor[NN];
__device__ int    g_bsum[SCAN_NB];
__device__ int    g_flag[SCAN_NB];
__device__ __align__(16) int2 g_srcw[NE + 2];
__device__ __align__(16) __half g_hh[(size_t)NN * H];      // GEMM out (gather source)
__device__ __align__(16) __half g_oh[3][(size_t)NN * H];   // layer outputs, fp16
__device__ __align__(16) __half g_whalf[3][H * H];         // fp16 W, row-major [k][n]
__device__ float  g_sums[6 * H];                           // fp32 stats; zeroed by prep

__device__ __forceinline__ uint32_t smem_u32(const void* p) {
    uint32_t a;
    asm("{ .reg .u64 t; cvta.to.shared.u64 t, %1; cvt.u32.u64 %0, t; }" : "=r"(a) : "l"(p));
    return a;
}

// BN scale/shift from accumulated sums (computed inline by consumers)
__device__ __forceinline__ void bn_from_sums(int layer, int c,
                                             const float* __restrict__ g,
                                             const float* __restrict__ be,
                                             float& sc, float& sh) {
    double s  = (double)g_sums[layer * 256 + c];
    double ss = (double)g_sums[layer * 256 + 128 + c];
    double mean = s * (1.0 / NN);
    double var  = ss * (1.0 / NN) - mean * mean;
    float inv = (float)(1.0 / sqrt(var + 1e-5));
    sc = g[c] * inv;
    sh = be[c] - (float)mean * sc;
}

// ---------------- launch 1: W fp16 prep + zero sums/flags + packed degcnt ----------------
__global__ void prep_kernel(const float* __restrict__ W1, const float* __restrict__ W2,
                            const float* __restrict__ W3,
                            const int* __restrict__ ei, const float* __restrict__ ew) {
    int b = blockIdx.x;
    if (b < PREPW_BLOCKS) {
        int l = b >> 6;
        const float* W = (l == 0) ? W1 : (l == 1) ? W2 : W3;
        int idx = (b & 63) * 256 + threadIdx.x;
        g_whalf[l][idx] = __float2half_rn(W[idx]);
        return;
    }
    if (b == PREPW_BLOCKS) {
        int t = threadIdx.x;
        #pragma unroll
        for (int k = 0; k < 3; k++) {
            int i = k * 256 + t;
            if (i < 6 * H) g_sums[i] = 0.f;
        }
        if (t < SCAN_NB) g_flag[t] = 0;
        return;
    }
    int e = (b - DEG_BASE) * 256 + threadIdx.x;
    if (e >= NE) return;
    int c = __ldcs(&ei[NE + e]);
    if ((unsigned)c >= NN) return;
    float w = __ldcs(&ew[e]);
    unsigned long long val =
        (1ULL << 40) | (unsigned long long)__float2uint_rn(w * 16777216.0f);
    atomicAdd(&g_pack[c], val);
}

// ---------------- launch 2: dis + single-kernel scan; restores g_pack=0 ----------------
__global__ void __launch_bounds__(1024) scandis_kernel() {
    __shared__ int wsum[32];
    __shared__ int s_pred[128];
    __shared__ int s_off;
    int tid = threadIdx.x, lane = tid & 31, wd = tid >> 5;
    int b = blockIdx.x;
    int i = b * 1024 + tid;

    int v = 0;
    if (i < NN) {
        unsigned long long p = g_pack[i];
        g_pack[i] = 0ULL;
        v = (int)(p >> 40);
        float deg = (float)((double)(p & 0xFFFFFFFFFFULL) * (1.0 / 16777216.0));
        g_dis[i] = rsqrtf(deg + 1.0f);   // +1 = self-loop weight
    }

    int x = v;
    #pragma unroll
    for (int off = 1; off < 32; off <<= 1) {
        int y = __shfl_up_sync(0xffffffffu, x, off);
        if (lane >= off) x += y;
    }
    if (lane == 31) wsum[wd] = x;
    __syncthreads();
    if (wd == 0) {
        int s = wsum[lane];
        #pragma unroll
        for (int off = 1; off < 32; off <<= 1) {
            int y = __shfl_up_sync(0xffffffffu, s, off);
            if (lane >= off) s += y;
        }
        wsum[lane] = s;
    }
    __syncthreads();
    int woff = wd ? wsum[wd - 1] : 0;
    int incl = x + woff;

    if (tid == 1023) {
        g_bsum[b] = incl;
        __threadfence();
        atomicExch(&g_flag[b], 1);
    }
    if (tid < b) {
        while (atomicAdd(&g_flag[tid], 0) == 0) {}
        __threadfence();
        s_pred[tid] = __ldcg(&g_bsum[tid]);
    }
    __syncthreads();
    int val = (tid < b) ? s_pred[tid] : 0;
    #pragma unroll
    for (int off = 16; off > 0; off >>= 1)
        val += __shfl_down_sync(0xffffffffu, val, off);
    __syncthreads();
    if (lane == 0) wsum[wd] = val;
    __syncthreads();
    if (tid == 0) {
        int s = 0;
        #pragma unroll
        for (int k = 0; k < 4; k++) s += wsum[k];
        s_off = s;
    }
    __syncthreads();
    int off2 = s_off;
    if (i < NN) {
        int rp = incl - v + off2;
        g_rowptr[i] = rp;
        g_cursor[i] = rp;
    }
    if (b == SCAN_NB - 1 && tid == 1023) g_rowptr[NN] = off2 + incl;
}

// ---------------- HMMA GEMM body ----------------
#define APAD 72
#define BPAD 136
__device__ __forceinline__ void gemm_body(
    const float* __restrict__ Aext, int osel, int bnlayer,
    const float* __restrict__ bng, const float* __restrict__ bnbe, int wsel, int bid,
    __half (*s_a)[APAD], __half (*s_b)[BPAD], float* s_sc, float* s_sh) {
    int tid = threadIdx.x, wid = tid >> 5, lane = tid & 31;
    int warp_m = wid & 3;
    int warp_n = wid >> 2;
    int m0 = bid * 128;
    bool dobn = (bnlayer >= 0);

    if (dobn && tid < H) {
        float sc, sh;
        bn_from_sums(bnlayer, tid, bng, bnbe, sc, sh);
        s_sc[tid] = sc;
        s_sh[tid] = sh;
    }
    __syncthreads();

    float d[2][8][4];
    #pragma unroll
    for (int mt = 0; mt < 2; mt++)
        #pragma unroll
        for (int nt = 0; nt < 8; nt++)
            #pragma unroll
            for (int r = 0; r < 4; r++) d[mt][nt][r] = 0.f;

    for (int kc = 0; kc < 2; kc++) {
        int kbase = kc * 64;
        #pragma unroll
        for (int i = 0; i < 8; i++) {
            int idx = i * 256 + tid;
            int m = idx >> 4, q = idx & 15;
            int gm = m0 + m;
            float4 v = make_float4(0.f, 0.f, 0.f, 0.f);
            if (gm < NN) {
                if (osel < 0) {
                    v = ((const float4*)Aext)[(size_t)gm * 32 + (kbase >> 2) + q];
                } else {
                    uint2 hv = *(const uint2*)&g_oh[osel][(size_t)gm * 128 + kbase + q * 4];
                    float2 f0 = __half22float2(*(__half2*)&hv.x);
                    float2 f1 = __half22float2(*(__half2*)&hv.y);
                    v = make_float4(f0.x, f0.y, f1.x, f1.y);
                }
                if (dobn) {
                    int k = kbase + q * 4;
                    v.x = fmaxf(fmaf(v.x, s_sc[k + 0], s_sh[k + 0]), 0.f);
                    v.y = fmaxf(fmaf(v.y, s_sc[k + 1], s_sh[k + 1]), 0.f);
                    v.z = fmaxf(fmaf(v.z, s_sc[k + 2], s_sh[k + 2]), 0.f);
                    v.w = fmaxf(fmaf(v.w, s_sc[k + 3], s_sh[k + 3]), 0.f);
                }
            }
            __half2 h0 = __floats2half2_rn(v.x, v.y);
            __half2 h1 = __floats2half2_rn(v.z, v.w);
            *(uint2*)&s_a[m][q * 4] = make_uint2(*(unsigned*)&h0, *(unsigned*)&h1);
        }
        #pragma unroll
        for (int i = 0; i < 4; i++) {
            int idx = i * 256 + tid;
            int k = idx >> 4, n16 = idx & 15;
            *(uint4*)&s_b[k][n16 * 8] =
                *(const uint4*)&g_whalf[wsel][(size_t)(kbase + k) * 128 + n16 * 8];
        }
        __syncthreads();

        #pragma unroll
        for (int kt = 0; kt < 4; kt++) {
            uint32_t a[2][4];
            #pragma unroll
            for (int mt = 0; mt < 2; mt++) {
                uint32_t addr = smem_u32(
                    &s_a[warp_m * 32 + mt * 16 + (lane & 15)][kt * 16 + (lane >> 4) * 8]);
                asm volatile("ldmatrix.sync.aligned.m8n8.x4.shared.b16 {%0,%1,%2,%3}, [%4];"
                             : "=r"(a[mt][0]), "=r"(a[mt][1]), "=r"(a[mt][2]), "=r"(a[mt][3])
                             : "r"(addr));
            }
            #pragma unroll
            for (int ng = 0; ng < 4; ng++) {
                uint32_t b0, b1, b2, b3;
                uint32_t addr = smem_u32(
                    &s_b[kt * 16 + (lane & 15)][warp_n * 64 + ng * 16 + (lane >> 4) * 8]);
                asm volatile("ldmatrix.sync.aligned.m8n8.x4.trans.shared.b16 {%0,%1,%2,%3}, [%4];"
                             : "=r"(b0), "=r"(b1), "=r"(b2), "=r"(b3) : "r"(addr));
                #pragma unroll
                for (int mt = 0; mt < 2; mt++) {
                    asm volatile(
                        "mma.sync.aligned.m16n8k16.row.col.f32.f16.f16.f32 "
                        "{%0,%1,%2,%3}, {%4,%5,%6,%7}, {%8,%9}, {%0,%1,%2,%3};"
                        : "+f"(d[mt][ng*2][0]), "+f"(d[mt][ng*2][1]),
                          "+f"(d[mt][ng*2][2]), "+f"(d[mt][ng*2][3])
                        : "r"(a[mt][0]), "r"(a[mt][1]), "r"(a[mt][2]), "r"(a[mt][3]),
                          "r"(b0), "r"(b1));
                    asm volatile(
                        "mma.sync.aligned.m16n8k16.row.col.f32.f16.f16.f32 "
                        "{%0,%1,%2,%3}, {%4,%5,%6,%7}, {%8,%9}, {%0,%1,%2,%3};"
                        : "+f"(d[mt][ng*2+1][0]), "+f"(d[mt][ng*2+1][1]),
                          "+f"(d[mt][ng*2+1][2]), "+f"(d[mt][ng*2+1][3])
                        : "r"(a[mt][0]), "r"(a[mt][1]), "r"(a[mt][2]), "r"(a[mt][3]),
                          "r"(b2), "r"(b3));
                }
            }
        }
        __syncthreads();
    }

    int mrow = m0 + warp_m * 32 + (lane >> 2);
    int ncol = warp_n * 64 + (lane & 3) * 2;
    #pragma unroll
    for (int mt = 0; mt < 2; mt++) {
        int r0 = mrow + mt * 16;
        int r1 = r0 + 8;
        #pragma unroll
        for (int nt = 0; nt < 8; nt++) {
            int c = ncol + nt * 8;
            if (r0 < NN) {
                __half2 h = __floats2half2_rn(d[mt][nt][0], d[mt][nt][1]);
                *(__half2*)&g_hh[(size_t)r0 * 128 + c] = h;
            }
            if (r1 < NN) {
                __half2 h = __floats2half2_rn(d[mt][nt][2], d[mt][nt][3]);
                *(__half2*)&g_hh[(size_t)r1 * 128 + c] = h;
            }
        }
    }
}

// ---------------- launch 3: fused fill (CSR) + gemm layer1 ----------------
__global__ void __launch_bounds__(256)
fillgemm_kernel(const float* __restrict__ x, const int* __restrict__ ei,
                const float* __restrict__ ew) {
    __shared__ __align__(16) __half s_a[128][APAD];
    __shared__ __align__(16) __half s_b[64][BPAD];
    __shared__ float s_sc[H], s_sh[H];
    if (blockIdx.x < GEMM_GRID) {
        gemm_body(x, -1, -1, nullptr, nullptr, 0, blockIdx.x, s_a, s_b, s_sc, s_sh);
        return;
    }
    int e = (blockIdx.x - GEMM_GRID) * 256 + threadIdx.x;
    if (e >= NE) return;
    int r = __ldcs(&ei[e]);
    int c = __ldcs(&ei[NE + e]);
    if ((unsigned)r >= NN || (unsigned)c >= NN) return;
    int pos = atomicAdd(&g_cursor[c], 1);
    float w = g_dis[r] * __ldcs(&ew[e]) * g_dis[c];
    g_srcw[pos] = make_int2(r, __float_as_int(w));
}

// gemm for layers 2/3 (fp16 A, BN computed inline from g_sums)
__global__ void __launch_bounds__(256)
gemm_kernel(int osel, int bnlayer, const float* __restrict__ bng,
            const float* __restrict__ bnbe, int wsel) {
    __shared__ __align__(16) __half s_a[128][APAD];
    __shared__ __align__(16) __half s_b[64][BPAD];
    __shared__ float s_sc[H], s_sh[H];
    gemm_body(nullptr, osel, bnlayer, bng, bnbe, wsel, blockIdx.x, s_a, s_b, s_sc, s_sh);
}

// ---------------- launch 4 (captured): agg, 256 thr, fp32 stats atomics ----------------
__device__ __forceinline__ void fma_half4(float4& acc, float w, unsigned lo, unsigned hi) {
    __half2 p0 = *(__half2*)&lo, p1 = *(__half2*)&hi;
    float2 f0 = __half22float2(p0), f1 = __half22float2(p1);
    acc.x = fmaf(w, f0.x, acc.x); acc.y = fmaf(w, f0.y, acc.y);
    acc.z = fmaf(w, f1.x, acc.z); acc.w = fmaf(w, f1.y, acc.w);
}

__global__ void __launch_bounds__(256, 6)
agg_kernel(const float* __restrict__ bias, int osel, int layer) {
    __shared__ float s_v[8][132];
    __half* outb = g_oh[osel];
    int wid  = threadIdx.x >> 5;
    int lane = threadIdx.x & 31;
    float4 b4 = ((const float4*)bias)[lane];
    float4 s4 = make_float4(0.f, 0.f, 0.f, 0.f);
    float4 q4 = make_float4(0.f, 0.f, 0.f, 0.f);
    int base = blockIdx.x * 64 + wid * 8;

    for (int n = 0; n < 8; n++) {
        int gw = base + n;
        if (gw < NN) {
            float dii = g_dis[gw];
            float swt = dii * dii;
            uint2 sv = __ldg((const uint2*)&g_hh[(size_t)gw * 128 + lane * 4]);
            float4 acc = make_float4(0.f, 0.f, 0.f, 0.f);
            fma_half4(acc, swt, sv.x, sv.y);
            int p  = __ldg(&g_rowptr[gw]);
            int pe = __ldg(&g_rowptr[gw + 1]);
            if ((p & 1) && p < pe) {
                int2  sw = __ldcs(&g_srcw[p]);
                uint2 v  = __ldg((const uint2*)&g_hh[(size_t)sw.x * 128 + lane * 4]);
                fma_half4(acc, __int_as_float(sw.y), v.x, v.y);
                ++p;
            }
            if (p + 3 < pe) {
                int4 c0 = __ldcs((const int4*)&g_srcw[p]);
                int4 c1 = __ldcs((const int4*)&g_srcw[p + 2]);
                for (; p + 7 < pe; p += 4) {
                    int4 n0 = __ldcs((const int4*)&g_srcw[p + 4]);
                    int4 n1 = __ldcs((const int4*)&g_srcw[p + 6]);
                    uint2 v0 = __ldg((const uint2*)&g_hh[(size_t)c0.x * 128 + lane * 4]);
                    uint2 v1 = __ldg((const uint2*)&g_hh[(size_t)c0.z * 128 + lane * 4]);
                    uint2 v2 = __ldg((const uint2*)&g_hh[(size_t)c1.x * 128 + lane * 4]);
                    uint2 v3 = __ldg((const uint2*)&g_hh[(size_t)c1.z * 128 + lane * 4]);
                    fma_half4(acc, __int_as_float(c0.y), v0.x, v0.y);
                    fma_half4(acc, __int_as_float(c0.w), v1.x, v1.y);
                    fma_half4(acc, __int_as_float(c1.y), v2.x, v2.y);
                    fma_half4(acc, __int_as_float(c1.w), v3.x, v3.y);
                    c0 = n0; c1 = n1;
                }
                uint2 v0 = __ldg((const uint2*)&g_hh[(size_t)c0.x * 128 + lane * 4]);
                uint2 v1 = __ldg((const uint2*)&g_hh[(size_t)c0.z * 128 + lane * 4]);
                uint2 v2 = __ldg((const uint2*)&g_hh[(size_t)c1.x * 128 + lane * 4]);
                uint2 v3 = __ldg((const uint2*)&g_hh[(size_t)c1.z * 128 + lane * 4]);
                fma_half4(acc, __int_as_float(c0.y), v0.x, v0.y);
                fma_half4(acc, __int_as_float(c0.w), v1.x, v1.y);
                fma_half4(acc, __int_as_float(c1.y), v2.x, v2.y);
                fma_half4(acc, __int_as_float(c1.w), v3.x, v3.y);
                p += 4;
            }
            for (; p < pe; ++p) {
                int2  sw = __ldcs(&g_srcw[p]);
                uint2 v  = __ldg((const uint2*)&g_hh[(size_t)sw.x * 128 + lane * 4]);
                fma_half4(acc, __int_as_float(sw.y), v.x, v.y);
            }
            acc.x += b4.x; acc.y += b4.y; acc.z += b4.z; acc.w += b4.w;
            __half2 h0 = __floats2half2_rn(acc.x, acc.y);
            __half2 h1 = __floats2half2_rn(acc.z, acc.w);
            *(uint2*)&outb[(size_t)gw * 128 + lane * 4] =
                make_uint2(*(unsigned*)&h0, *(unsigned*)&h1);
            s4.x += acc.x; s4.y += acc.y; s4.z += acc.z; s4.w += acc.w;
            q4.x = fmaf(acc.x, acc.x, q4.x); q4.y = fmaf(acc.y, acc.y, q4.y);
            q4.z = fmaf(acc.z, acc.z, q4.z); q4.w = fmaf(acc.w, acc.w, q4.w);
        }
    }

    *((float4*)&s_v[wid][lane * 4]) = s4;
    __syncthreads();
    int c = threadIdx.x;
    if (c < 128) {
        float s = 0.f;
        #pragma unroll
        for (int w8 = 0; w8 < 8; w8++) s += s_v[w8][c];
        atomicAdd(&g_sums[layer * 256 + c], s);
    }
    __syncthreads();
    *((float4*)&s_v[wid][lane * 4]) = q4;
    __syncthreads();
    if (c < 128) {
        float q = 0.f;
        #pragma unroll
        for (int w8 = 0; w8 < 8; w8++) q += s_v[w8][c];
        atomicAdd(&g_sums[layer * 256 + 128 + c], q);
    }
}

// ---------------- readout (BN computed inline for all 3 layers) ----------------
__global__ void __launch_bounds__(320)
linear_kernel(const float* __restrict__ Wlin, const float* __restrict__ blin,
              const float* __restrict__ g1, const float* __restrict__ be1,
              const float* __restrict__ g2, const float* __restrict__ be2,
              const float* __restrict__ g3, const float* __restrict__ be3,
              float* __restrict__ out) {
    __shared__ float s_wt[10][388];
    __shared__ float s_emb[32][388];
    __shared__ float s_b[10];
    __shared__ float s_sc[384], s_sh[384];
    int tid = threadIdx.x;
    for (int i = tid; i < 3840; i += 320) s_wt[i % 10][i / 10] = Wlin[i];
    for (int i = tid; i < 384; i += 320) {
        int l = i >> 7, c = i & 127;
        const float* g  = (l == 0) ? g1  : (l == 1) ? g2  : g3;
        const float* be = (l == 0) ? be1 : (l == 1) ? be2 : be3;
        float sc, sh;
        bn_from_sums(l, c, g, be, sc, sh);
        s_sc[i] = sc;
        s_sh[i] = sh;
    }
    if (tid < 10) s_b[tid] = blin[tid];
    int nb = blockIdx.x * 32;
    __syncthreads();

    for (int i = tid; i < 3072; i += 320) {
        int node = i / 96, q = i % 96;
        int gn = nb + node;
        float4 v = make_float4(0.f, 0.f, 0.f, 0.f);
        if (gn < NN) {
            int l = q >> 5, qq = q & 31;
            uint2 hv = *(const uint2*)&g_oh[l][(size_t)gn * 128 + qq * 4];
            float2 f0 = __half22float2(*(__half2*)&hv.x);
            float2 f1 = __half22float2(*(__half2*)&hv.y);
            v = make_float4(f0.x, f0.y, f1.x, f1.y);
        }
        int f = q * 4;
        v.x = fmaxf(fmaf(v.x, s_sc[f + 0], s_sh[f + 0]), 0.f);
        v.y = fmaxf(fmaf(v.y, s_sc[f + 1], s_sh[f + 1]), 0.f);
        v.z = fmaxf(fmaf(v.z, s_sc[f + 2], s_sh[f + 2]), 0.f);
        v.w = fmaxf(fmaf(v.w, s_sc[f + 3], s_sh[f + 3]), 0.f);
        *((float4*)&s_emb[node][f]) = v;
    }
    __syncthreads();

    int node = tid / 10, c = tid % 10;
    int gn = nb + node;
    if (gn < NN) {
        const float4* e = (const float4*)&s_emb[node][0];
        const float4* w = (const float4*)&s_wt[c][0];
        float acc = 0.f;
        #pragma unroll
        for (int j = 0; j < 96; j++) {
            float4 v = e[j], ww = w[j];
            acc += v.x * ww.x + v.y * ww.y + v.z * ww.z + v.w * ww.w;
        }
        out[(size_t)gn * 10 + c] = acc + s_b[c];
    }
}

// ---------------- host launcher ----------------
extern "C" void kernel_launch(void* const* d_in, const int* in_sizes, int n_in,
                              void* d_out, int out_size) {
    const float* x    = (const float*)d_in[0];
    const int*   ei   = (const int*)d_in[1];
    const float* ew   = (const float*)d_in[2];
    const float* W1  = (const float*)d_in[3];
    const float* b1  = (const float*)d_in[4];
    const float* g1  = (const float*)d_in[5];
    const float* be1 = (const float*)d_in[6];
    const float* W2  = (const float*)d_in[7];
    const float* b2  = (const float*)d_in[8];
    const float* g2  = (const float*)d_in[9];
    const float* be2 = (const float*)d_in[10];
    const float* W3  = (const float*)d_in[11];
    const float* b3  = (const float*)d_in[12];
    const float* g3  = (const float*)d_in[13];
    const float* be3 = (const float*)d_in[14];
    const float* Wlin = (const float*)d_in[15];
    const float* blin = (const float*)d_in[16];
    float* out = (float*)d_out;

    prep_kernel<<<DEG_BASE + FILL_GRID, 256>>>(W1, W2, W3, ei, ew);  // 1
    scandis_kernel<<<SCAN_NB, 1024>>>();                             // 2
    fillgemm_kernel<<<GEMM_GRID + FILL_GRID, 256>>>(x, ei, ew);      // 3
    agg_kernel<<<AGG_GRID, 256>>>(b1, 0, 0);                         // 4 <- ncu slot

    gemm_kernel<<<GEMM_GRID, 256>>>(0, 0, g1, be1, 1);               // 5
    agg_kernel<<<AGG_GRID, 256>>>(b2, 1, 1);                         // 6
    gemm_kernel<<<GEMM_GRID, 256>>>(1, 1, g2, be2, 2);               // 7
    agg_kernel<<<AGG_GRID, 256>>>(b3, 2, 2);                         // 8
    linear_kernel<<<(NN + 31) / 32, 320>>>(Wlin, blin, g1, be1, g2, be2, g3, be3, out); // 9
    (void)in_sizes; (void)n_in; (void)out_size;
}

// round 14
// speedup vs baseline: 1.2070x; 1.0406x over previous
#include <cuda_runtime.h>
#include <cuda_fp16.h>
#include <cstdint>

#define NN 100000
#define NE 1600000
#define H  128
#define SCAN_NB 98           // ceil(NN/1024)
#define GEMM_GRID 782        // ceil(NN/128)
#define FILL_GRID 6250       // NE/256
#define AGG_GRID 1563        // ceil(NN/64), 256-thr blocks
#define PREPW_BLOCKS 192     // 3 layers x 64 blocks
#define DEG_BASE 193         // degcnt blocks start here in prep_kernel

// ---------------- scratch (zero at load; every call restores zeros after use) ----------
__device__ unsigned long long g_pack[NN];   // cnt<<40 | fixed-point weighted degree
__device__ float  g_dis[NN];
__device__ int    g_rowptr[NN + 1];
__device__ int    g_cursor[NN];
__device__ int    g_bsum[SCAN_NB];
__device__ int    g_flag[SCAN_NB];
__device__ __align__(16) int2 g_srcw[NE + NN + 2];         // even-padded CSR
__device__ __align__(16) __half g_hh[(size_t)NN * H];      // GEMM out (gather source)
__device__ __align__(16) __half g_oh[3][(size_t)NN * H];   // layer outputs, fp16
__device__ __align__(16) __half g_whalf[3][H * H];         // fp16 W, row-major [k][n]
__device__ float  g_sums[6 * H];                           // fp32 stats; zeroed by prep

__device__ __forceinline__ uint32_t smem_u32(const void* p) {
    uint32_t a;
    asm("{ .reg .u64 t; cvta.to.shared.u64 t, %1; cvt.u32.u64 %0, t; }" : "=r"(a) : "l"(p));
    return a;
}

// BN scale/shift from accumulated sums (computed inline by consumers)
__device__ __forceinline__ void bn_from_sums(int layer, int c,
                                             const float* __restrict__ g,
                                             const float* __restrict__ be,
                                             float& sc, float& sh) {
    double s  = (double)g_sums[layer * 256 + c];
    double ss = (double)g_sums[layer * 256 + 128 + c];
    double mean = s * (1.0 / NN);
    double var  = ss * (1.0 / NN) - mean * mean;
    float inv = (float)(1.0 / sqrt(var + 1e-5));
    sc = g[c] * inv;
    sh = be[c] - (float)mean * sc;
}

// ---------------- launch 1: W fp16 prep + zero sums/flags + packed degcnt ----------------
__global__ void prep_kernel(const float* __restrict__ W1, const float* __restrict__ W2,
                            const float* __restrict__ W3,
                            const int* __restrict__ ei, const float* __restrict__ ew) {
    int b = blockIdx.x;
    if (b < PREPW_BLOCKS) {
        int l = b >> 6;
        const float* W = (l == 0) ? W1 : (l == 1) ? W2 : W3;
        int idx = (b & 63) * 256 + threadIdx.x;
        g_whalf[l][idx] = __float2half_rn(W[idx]);
        return;
    }
    if (b == PREPW_BLOCKS) {
        int t = threadIdx.x;
        #pragma unroll
        for (int k = 0; k < 3; k++) {
            int i = k * 256 + t;
            if (i < 6 * H) g_sums[i] = 0.f;
        }
        if (t < SCAN_NB) g_flag[t] = 0;
        return;
    }
    int e = (b - DEG_BASE) * 256 + threadIdx.x;
    if (e >= NE) return;
    int c = __ldcs(&ei[NE + e]);
    if ((unsigned)c >= NN) return;
    float w = __ldcs(&ew[e]);
    unsigned long long val =
        (1ULL << 40) | (unsigned long long)__float2uint_rn(w * 16777216.0f);
    atomicAdd(&g_pack[c], val);
}

// ---------------- launch 2: dis + single-kernel scan over even-padded counts ------------
__global__ void __launch_bounds__(1024) scandis_kernel() {
    __shared__ int wsum[32];
    __shared__ int s_pred[128];
    __shared__ int s_off;
    int tid = threadIdx.x, lane = tid & 31, wd = tid >> 5;
    int b = blockIdx.x;
    int i = b * 1024 + tid;

    int v = 0;
    if (i < NN) {
        unsigned long long p = g_pack[i];
        g_pack[i] = 0ULL;
        v = (int)(p >> 40);
        float deg = (float)((double)(p & 0xFFFFFFFFFFULL) * (1.0 / 16777216.0));
        g_dis[i] = rsqrtf(deg + 1.0f);   // +1 = self-loop weight
    }
    int vpad = v + (v & 1);              // even-pad each node's slot count

    int x = vpad;
    #pragma unroll
    for (int off = 1; off < 32; off <<= 1) {
        int y = __shfl_up_sync(0xffffffffu, x, off);
        if (lane >= off) x += y;
    }
    if (lane == 31) wsum[wd] = x;
    __syncthreads();
    if (wd == 0) {
        int s = wsum[lane];
        #pragma unroll
        for (int off = 1; off < 32; off <<= 1) {
            int y = __shfl_up_sync(0xffffffffu, s, off);
            if (lane >= off) s += y;
        }
        wsum[lane] = s;
    }
    __syncthreads();
    int woff = wd ? wsum[wd - 1] : 0;
    int incl = x + woff;

    if (tid == 1023) {
        g_bsum[b] = incl;
        __threadfence();
        atomicExch(&g_flag[b], 1);
    }
    if (tid < b) {
        while (atomicAdd(&g_flag[tid], 0) == 0) {}
        __threadfence();
        s_pred[tid] = __ldcg(&g_bsum[tid]);
    }
    __syncthreads();
    int val = (tid < b) ? s_pred[tid] : 0;
    #pragma unroll
    for (int off = 16; off > 0; off >>= 1)
        val += __shfl_down_sync(0xffffffffu, val, off);
    __syncthreads();
    if (lane == 0) wsum[wd] = val;
    __syncthreads();
    if (tid == 0) {
        int s = 0;
        #pragma unroll
        for (int k = 0; k < 4; k++) s += wsum[k];
        s_off = s;
    }
    __syncthreads();
    int off2 = s_off;
    if (i < NN) {
        int rp = incl - vpad + off2;
        g_rowptr[i] = rp;
        g_cursor[i] = rp;
        if (v & 1) g_srcw[rp + v] = make_int2(0, 0);   // sentinel: w=0
    }
    if (b == SCAN_NB - 1 && tid == 1023) g_rowptr[NN] = off2 + incl;
}

// ---------------- HMMA GEMM body ----------------
#define APAD 72
#define BPAD 136
__device__ __forceinline__ void gemm_body(
    const float* __restrict__ Aext, int osel, int bnlayer,
    const float* __restrict__ bng, const float* __restrict__ bnbe, int wsel, int bid,
    __half (*s_a)[APAD], __half (*s_b)[BPAD], float* s_sc, float* s_sh) {
    int tid = threadIdx.x, wid = tid >> 5, lane = tid & 31;
    int warp_m = wid & 3;
    int warp_n = wid >> 2;
    int m0 = bid * 128;
    bool dobn = (bnlayer >= 0);

    if (dobn && tid < H) {
        float sc, sh;
        bn_from_sums(bnlayer, tid, bng, bnbe, sc, sh);
        s_sc[tid] = sc;
        s_sh[tid] = sh;
    }
    __syncthreads();

    float d[2][8][4];
    #pragma unroll
    for (int mt = 0; mt < 2; mt++)
        #pragma unroll
        for (int nt = 0; nt < 8; nt++)
            #pragma unroll
            for (int r = 0; r < 4; r++) d[mt][nt][r] = 0.f;

    for (int kc = 0; kc < 2; kc++) {
        int kbase = kc * 64;
        #pragma unroll
        for (int i = 0; i < 8; i++) {
            int idx = i * 256 + tid;
            int m = idx >> 4, q = idx & 15;
            int gm = m0 + m;
            float4 v = make_float4(0.f, 0.f, 0.f, 0.f);
            if (gm < NN) {
                if (osel < 0) {
                    v = ((const float4*)Aext)[(size_t)gm * 32 + (kbase >> 2) + q];
                } else {
                    uint2 hv = *(const uint2*)&g_oh[osel][(size_t)gm * 128 + kbase + q * 4];
                    float2 f0 = __half22float2(*(__half2*)&hv.x);
                    float2 f1 = __half22float2(*(__half2*)&hv.y);
                    v = make_float4(f0.x, f0.y, f1.x, f1.y);
                }
                if (dobn) {
                    int k = kbase + q * 4;
                    v.x = fmaxf(fmaf(v.x, s_sc[k + 0], s_sh[k + 0]), 0.f);
                    v.y = fmaxf(fmaf(v.y, s_sc[k + 1], s_sh[k + 1]), 0.f);
                    v.z = fmaxf(fmaf(v.z, s_sc[k + 2], s_sh[k + 2]), 0.f);
                    v.w = fmaxf(fmaf(v.w, s_sc[k + 3], s_sh[k + 3]), 0.f);
                }
            }
            __half2 h0 = __floats2half2_rn(v.x, v.y);
            __half2 h1 = __floats2half2_rn(v.z, v.w);
            *(uint2*)&s_a[m][q * 4] = make_uint2(*(unsigned*)&h0, *(unsigned*)&h1);
        }
        #pragma unroll
        for (int i = 0; i < 4; i++) {
            int idx = i * 256 + tid;
            int k = idx >> 4, n16 = idx & 15;
            *(uint4*)&s_b[k][n16 * 8] =
                *(const uint4*)&g_whalf[wsel][(size_t)(kbase + k) * 128 + n16 * 8];
        }
        __syncthreads();

        #pragma unroll
        for (int kt = 0; kt < 4; kt++) {
            uint32_t a[2][4];
            #pragma unroll
            for (int mt = 0; mt < 2; mt++) {
                uint32_t addr = smem_u32(
                    &s_a[warp_m * 32 + mt * 16 + (lane & 15)][kt * 16 + (lane >> 4) * 8]);
                asm volatile("ldmatrix.sync.aligned.m8n8.x4.shared.b16 {%0,%1,%2,%3}, [%4];"
                             : "=r"(a[mt][0]), "=r"(a[mt][1]), "=r"(a[mt][2]), "=r"(a[mt][3])
                             : "r"(addr));
            }
            #pragma unroll
            for (int ng = 0; ng < 4; ng++) {
                uint32_t b0, b1, b2, b3;
                uint32_t addr = smem_u32(
                    &s_b[kt * 16 + (lane & 15)][warp_n * 64 + ng * 16 + (lane >> 4) * 8]);
                asm volatile("ldmatrix.sync.aligned.m8n8.x4.trans.shared.b16 {%0,%1,%2,%3}, [%4];"
                             : "=r"(b0), "=r"(b1), "=r"(b2), "=r"(b3) : "r"(addr));
                #pragma unroll
                for (int mt = 0; mt < 2; mt++) {
                    asm volatile(
                        "mma.sync.aligned.m16n8k16.row.col.f32.f16.f16.f32 "
                        "{%0,%1,%2,%3}, {%4,%5,%6,%7}, {%8,%9}, {%0,%1,%2,%3};"
                        : "+f"(d[mt][ng*2][0]), "+f"(d[mt][ng*2][1]),
                          "+f"(d[mt][ng*2][2]), "+f"(d[mt][ng*2][3])
                        : "r"(a[mt][0]), "r"(a[mt][1]), "r"(a[mt][2]), "r"(a[mt][3]),
                          "r"(b0), "r"(b1));
                    asm volatile(
                        "mma.sync.aligned.m16n8k16.row.col.f32.f16.f16.f32 "
                        "{%0,%1,%2,%3}, {%4,%5,%6,%7}, {%8,%9}, {%0,%1,%2,%3};"
                        : "+f"(d[mt][ng*2+1][0]), "+f"(d[mt][ng*2+1][1]),
                          "+f"(d[mt][ng*2+1][2]), "+f"(d[mt][ng*2+1][3])
                        : "r"(a[mt][0]), "r"(a[mt][1]), "r"(a[mt][2]), "r"(a[mt][3]),
                          "r"(b2), "r"(b3));
                }
            }
        }
        __syncthreads();
    }

    int mrow = m0 + warp_m * 32 + (lane >> 2);
    int ncol = warp_n * 64 + (lane & 3) * 2;
    #pragma unroll
    for (int mt = 0; mt < 2; mt++) {
        int r0 = mrow + mt * 16;
        int r1 = r0 + 8;
        #pragma unroll
        for (int nt = 0; nt < 8; nt++) {
            int c = ncol + nt * 8;
            if (r0 < NN) {
                __half2 h = __floats2half2_rn(d[mt][nt][0], d[mt][nt][1]);
                *(__half2*)&g_hh[(size_t)r0 * 128 + c] = h;
            }
            if (r1 < NN) {
                __half2 h = __floats2half2_rn(d[mt][nt][2], d[mt][nt][3]);
                *(__half2*)&g_hh[(size_t)r1 * 128 + c] = h;
            }
        }
    }
}

// ---------------- launch 3: fused fill (CSR) + gemm layer1 ----------------
__global__ void __launch_bounds__(256)
fillgemm_kernel(const float* __restrict__ x, const int* __restrict__ ei,
                const float* __restrict__ ew) {
    __shared__ __align__(16) __half s_a[128][APAD];
    __shared__ __align__(16) __half s_b[64][BPAD];
    __shared__ float s_sc[H], s_sh[H];
    if (blockIdx.x < GEMM_GRID) {
        gemm_body(x, -1, -1, nullptr, nullptr, 0, blockIdx.x, s_a, s_b, s_sc, s_sh);
        return;
    }
    int e = (blockIdx.x - GEMM_GRID) * 256 + threadIdx.x;
    if (e >= NE) return;
    int r = __ldcs(&ei[e]);
    int c = __ldcs(&ei[NE + e]);
    if ((unsigned)r >= NN || (unsigned)c >= NN) return;
    int pos = atomicAdd(&g_cursor[c], 1);
    float w = g_dis[r] * __ldcs(&ew[e]) * g_dis[c];
    g_srcw[pos] = make_int2(r, __float_as_int(w));
}

// gemm for layers 2/3 (fp16 A, BN computed inline from g_sums)
__global__ void __launch_bounds__(256)
gemm_kernel(int osel, int bnlayer, const float* __restrict__ bng,
            const float* __restrict__ bnbe, int wsel) {
    __shared__ __align__(16) __half s_a[128][APAD];
    __shared__ __align__(16) __half s_b[64][BPAD];
    __shared__ float s_sc[H], s_sh[H];
    gemm_body(nullptr, osel, bnlayer, bng, bnbe, wsel, blockIdx.x, s_a, s_b, s_sc, s_sh);
}

// ---------------- launch 4 (captured): agg, even CSR, branch-free edge loop ------------
__device__ __forceinline__ void fma_half4(float4& acc, float w, unsigned lo, unsigned hi) {
    __half2 p0 = *(__half2*)&lo, p1 = *(__half2*)&hi;
    float2 f0 = __half22float2(p0), f1 = __half22float2(p1);
    acc.x = fmaf(w, f0.x, acc.x); acc.y = fmaf(w, f0.y, acc.y);
    acc.z = fmaf(w, f1.x, acc.z); acc.w = fmaf(w, f1.y, acc.w);
}

__global__ void __launch_bounds__(256, 6)
agg_kernel(const float* __restrict__ bias, int osel, int layer) {
    __shared__ float s_v[8][132];
    __half* outb = g_oh[osel];
    int wid  = threadIdx.x >> 5;
    int lane = threadIdx.x & 31;
    float4 b4 = ((const float4*)bias)[lane];
    float4 s4 = make_float4(0.f, 0.f, 0.f, 0.f);
    float4 q4 = make_float4(0.f, 0.f, 0.f, 0.f);
    int base = blockIdx.x * 64 + wid * 8;
    const uint2* hv = (const uint2*)g_hh + lane;   // lane-fixed channel offset

    for (int n = 0; n < 8; n++) {
        int gw = base + n;
        if (gw < NN) {
            float dii = g_dis[gw];
            float swt = dii * dii;
            uint2 sv = __ldg(&hv[(size_t)gw * 32]);
            float4 acc = make_float4(0.f, 0.f, 0.f, 0.f);
            fma_half4(acc, swt, sv.x, sv.y);
            int p  = __ldg(&g_rowptr[gw]);       // even
            int pe = __ldg(&g_rowptr[gw + 1]);   // even
            #pragma unroll 2
            for (; p < pe; p += 2) {
                int4 c0 = *(const int4*)&g_srcw[p];
                uint2 v0 = __ldg(&hv[(size_t)c0.x * 32]);
                uint2 v1 = __ldg(&hv[(size_t)c0.z * 32]);
                fma_half4(acc, __int_as_float(c0.y), v0.x, v0.y);
                fma_half4(acc, __int_as_float(c0.w), v1.x, v1.y);
            }
            acc.x += b4.x; acc.y += b4.y; acc.z += b4.z; acc.w += b4.w;
            __half2 h0 = __floats2half2_rn(acc.x, acc.y);
            __half2 h1 = __floats2half2_rn(acc.z, acc.w);
            *(uint2*)&outb[(size_t)gw * 128 + lane * 4] =
                make_uint2(*(unsigned*)&h0, *(unsigned*)&h1);
            s4.x += acc.x; s4.y += acc.y; s4.z += acc.z; s4.w += acc.w;
            q4.x = fmaf(acc.x, acc.x, q4.x); q4.y = fmaf(acc.y, acc.y, q4.y);
            q4.z = fmaf(acc.z, acc.z, q4.z); q4.w = fmaf(acc.w, acc.w, q4.w);
        }
    }

    *((float4*)&s_v[wid][lane * 4]) = s4;
    __syncthreads();
    int c = threadIdx.x;
    if (c < 128) {
        float s = 0.f;
        #pragma unroll
        for (int w8 = 0; w8 < 8; w8++) s += s_v[w8][c];
        atomicAdd(&g_sums[layer * 256 + c], s);
    }
    __syncthreads();
    *((float4*)&s_v[wid][lane * 4]) = q4;
    __syncthreads();
    if (c < 128) {
        float q = 0.f;
        #pragma unroll
        for (int w8 = 0; w8 < 8; w8++) q += s_v[w8][c];
        atomicAdd(&g_sums[layer * 256 + 128 + c], q);
    }
}

// ---------------- readout (BN computed inline for all 3 layers) ----------------
__global__ void __launch_bounds__(320)
linear_kernel(const float* __restrict__ Wlin, const float* __restrict__ blin,
              const float* __restrict__ g1, const float* __restrict__ be1,
              const float* __restrict__ g2, const float* __restrict__ be2,
              const float* __restrict__ g3, const float* __restrict__ be3,
              float* __restrict__ out) {
    __shared__ float s_wt[10][388];
    __shared__ float s_emb[32][388];
    __shared__ float s_b[10];
    __shared__ float s_sc[384], s_sh[384];
    int tid = threadIdx.x;
    for (int i = tid; i < 3840; i += 320) s_wt[i % 10][i / 10] = Wlin[i];
    for (int i = tid; i < 384; i += 320) {
        int l = i >> 7, c = i & 127;
        const float* g  = (l == 0) ? g1  : (l == 1) ? g2  : g3;
        const float* be = (l == 0) ? be1 : (l == 1) ? be2 : be3;
        float sc, sh;
        bn_from_sums(l, c, g, be, sc, sh);
        s_sc[i] = sc;
        s_sh[i] = sh;
    }
    if (tid < 10) s_b[tid] = blin[tid];
    int nb = blockIdx.x * 32;
    __syncthreads();

    for (int i = tid; i < 3072; i += 320) {
        int node = i / 96, q = i % 96;
        int gn = nb + node;
        float4 v = make_float4(0.f, 0.f, 0.f, 0.f);
        if (gn < NN) {
            int l = q >> 5, qq = q & 31;
            uint2 hv = *(const uint2*)&g_oh[l][(size_t)gn * 128 + qq * 4];
            float2 f0 = __half22float2(*(__half2*)&hv.x);
            float2 f1 = __half22float2(*(__half2*)&hv.y);
            v = make_float4(f0.x, f0.y, f1.x, f1.y);
        }
        int f = q * 4;
        v.x = fmaxf(fmaf(v.x, s_sc[f + 0], s_sh[f + 0]), 0.f);
        v.y = fmaxf(fmaf(v.y, s_sc[f + 1], s_sh[f + 1]), 0.f);
        v.z = fmaxf(fmaf(v.z, s_sc[f + 2], s_sh[f + 2]), 0.f);
        v.w = fmaxf(fmaf(v.w, s_sc[f + 3], s_sh[f + 3]), 0.f);
        *((float4*)&s_emb[node][f]) = v;
    }
    __syncthreads();

    int node = tid / 10, c = tid % 10;
    int gn = nb + node;
    if (gn < NN) {
        const float4* e = (const float4*)&s_emb[node][0];
        const float4* w = (const float4*)&s_wt[c][0];
        float acc = 0.f;
        #pragma unroll
        for (int j = 0; j < 96; j++) {
            float4 v = e[j], ww = w[j];
            acc += v.x * ww.x + v.y * ww.y + v.z * ww.z + v.w * ww.w;
        }
        out[(size_t)gn * 10 + c] = acc + s_b[c];
    }
}

// ---------------- host launcher ----------------
extern "C" void kernel_launch(void* const* d_in, const int* in_sizes, int n_in,
                              void* d_out, int out_size) {
    const float* x    = (const float*)d_in[0];
    const int*   ei   = (const int*)d_in[1];
    const float* ew   = (const float*)d_in[2];
    const float* W1  = (const float*)d_in[3];
    const float* b1  = (const float*)d_in[4];
    const float* g1  = (const float*)d_in[5];
    const float* be1 = (const float*)d_in[6];
    const float* W2  = (const float*)d_in[7];
    const float* b2  = (const float*)d_in[8];
    const float* g2  = (const float*)d_in[9];
    const float* be2 = (const float*)d_in[10];
    const float* W3  = (const float*)d_in[11];
    const float* b3  = (const float*)d_in[12];
    const float* g3  = (const float*)d_in[13];
    const float* be3 = (const float*)d_in[14];
    const float* Wlin = (const float*)d_in[15];
    const float* blin = (const float*)d_in[16];
    float* out = (float*)d_out;

    prep_kernel<<<DEG_BASE + FILL_GRID, 256>>>(W1, W2, W3, ei, ew);  // 1
    scandis_kernel<<<SCAN_NB, 1024>>>();                             // 2
    fillgemm_kernel<<<GEMM_GRID + FILL_GRID, 256>>>(x, ei, ew);      // 3
    agg_kernel<<<AGG_GRID, 256>>>(b1, 0, 0);                         // 4 <- ncu slot

    gemm_kernel<<<GEMM_GRID, 256>>>(0, 0, g1, be1, 1);               // 5
    agg_kernel<<<AGG_GRID, 256>>>(b2, 1, 1);                         // 6
    gemm_kernel<<<GEMM_GRID, 256>>>(1, 1, g2, be2, 2);               // 7
    agg_kernel<<<AGG_GRID, 256>>>(b3, 2, 2);                         // 8
    linear_kernel<<<(NN + 31) / 32, 320>>>(Wlin, blin, g1, be1, g2, be2, g3, be3, out); // 9
    (void)in_sizes; (void)n_in; (void)out_size;
}